// round 7
// baseline (speedup 1.0000x reference)
#include <cuda_runtime.h>
#include <cstdint>

// 2D acoustic FDTD, 500 steps, 8 shots, 256x256, 128 recs/shot.
// One persistent kernel; shot = CSZ-CTA cluster; fields in SMEM + registers.
// Neighbor-only sync via monotonic DSMEM progress flags (cluster-size-indep).
// Preferred CSZ=16 (128 CTAs -> 128 SMs), fallback CSZ=8.

#define DT 0.001f
#define DX 10.0f

constexpr int NT   = 500;
constexpr int NS   = 8;
constexpr int NZ   = 256;
constexpr int NXC  = 256;
constexpr int NREC = 128;

constexpr int NTHREADS = 1024;
constexpr int COL4 = NXC / 4;           // 64
constexpr int RG   = NTHREADS / COL4;   // 16 row-groups

// ---------------------------------------------------------------- PTX helpers
__device__ __forceinline__ uint32_t cvta_smem(const void* p) {
    return (uint32_t)__cvta_generic_to_shared(p);
}
__device__ __forceinline__ uint32_t mapa_cluster(uint32_t laddr, uint32_t rank) {
    uint32_t r;
    asm("mapa.shared::cluster.u32 %0, %1, %2;" : "=r"(r) : "r"(laddr), "r"(rank));
    return r;
}
__device__ __forceinline__ float4 ld_dsmem_v4(uint32_t addr) {
    float4 v;
    asm volatile("ld.shared::cluster.v4.f32 {%0,%1,%2,%3}, [%4];"
                 : "=f"(v.x), "=f"(v.y), "=f"(v.z), "=f"(v.w) : "r"(addr));
    return v;
}
__device__ __forceinline__ void cluster_sync_() {
    asm volatile("barrier.cluster.arrive.aligned;" ::: "memory");
    asm volatile("barrier.cluster.wait.aligned;" ::: "memory");
}
__device__ __forceinline__ uint32_t cluster_rank_() {
    uint32_t r;
    asm("mov.u32 %0, %%cluster_ctarank;" : "=r"(r));
    return r;
}
// monotonic progress flags: remote release-store, local acquire-load spin
__device__ __forceinline__ void st_flag_remote(uint32_t addr, uint32_t val) {
    asm volatile("st.release.cluster.shared::cluster.u32 [%0], %1;"
                 :: "r"(addr), "r"(val) : "memory");
}
__device__ __forceinline__ uint32_t ld_flag_acq(uint32_t addr) {
    uint32_t v;
    asm volatile("ld.acquire.cluster.shared::cta.u32 %0, [%1];"
                 : "=r"(v) : "r"(addr) : "memory");
    return v;
}

// ---------------------------------------------------------------- kernel
template<int CSZ>
__global__ void __launch_bounds__(NTHREADS, 1)
wave_kernel(const float* __restrict__ x,     // (NT, NS)
            const float* __restrict__ vp,    // (NZ, NXC)
            const int*   __restrict__ src,   // (NS, 2)
            const int*   __restrict__ rec,   // (NS, NREC, 2)
            float*       __restrict__ out)   // (NT, NS, NREC)
{
    constexpr int ROWS = NZ / CSZ;          // 16 or 32
    constexpr int RPT  = ROWS / RG;         // 1 or 2
    constexpr int BUF_ELEMS = ROWS * NXC;

    extern __shared__ float sm[];
    float* buf0 = sm;
    float* buf1 = sm + BUF_ELEMS;
    float* xs   = sm + 2 * BUF_ELEMS;

    __shared__ unsigned int flag_n, flag_s;   // neighbor progress counters
    __shared__ int rcnt;
    __shared__ int2 rlist[NREC];

    const int tid  = threadIdx.x;
    const uint32_t rank = cluster_rank_();
    const int shot = blockIdx.x / CSZ;

    const int col4 = tid & (COL4 - 1);
    const int rg   = tid >> 6;           // 0..15
    const int lr0  = rg * RPT;
    const int xcol = col4 * 4;
    const bool has_n = (rank > 0);
    const bool has_s = (rank < CSZ - 1);

    // --- init ----------------------------------------------------------------
    for (int i = tid; i < BUF_ELEMS; i += NTHREADS) { buf0[i] = 0.f; buf1[i] = 0.f; }
    for (int i = tid; i < NT; i += NTHREADS) xs[i] = x[i * NS + shot];
    if (tid == 0) { rcnt = 0; flag_n = 0; flag_s = 0; }
    __syncthreads();

    // claim receivers owned by this CTA
    if (tid < NREC) {
        const int gi = shot * NREC + tid;
        const int rz = rec[gi * 2 + 0];
        const int rx = rec[gi * 2 + 1];
        if (rz / ROWS == (int)rank) {
            int s = atomicAdd(&rcnt, 1);
            rlist[s] = make_int2((rz % ROWS) * NXC + rx, shot * NREC + tid);
        }
    }

    // c2 in registers
    float4 c2r[RPT];
    const float sc = DT / DX;
#pragma unroll
    for (int j = 0; j < RPT; j++) {
        const int g = (int)rank * ROWS + lr0 + j;
        float4 v = *(const float4*)(vp + g * NXC + xcol);
        float a = v.x * sc, b = v.y * sc, c = v.z * sc, d = v.w * sc;
        c2r[j] = make_float4(a * a, b * b, c * c, d * d);
    }

    // field registers: prev and cur (zero at t=0)
    float4 pr[RPT], cC[RPT];
#pragma unroll
    for (int j = 0; j < RPT; j++) {
        pr[j] = make_float4(0.f, 0.f, 0.f, 0.f);
        cC[j] = make_float4(0.f, 0.f, 0.f, 0.f);
    }

    // source ownership
    const int sz = src[shot * 2 + 0];
    const int sx = src[shot * 2 + 1];
    const int sj = sz - ((int)rank * ROWS + lr0);
    const bool shere = (sj >= 0 && sj < RPT && sx >= xcol && sx < xcol + 4);
    const int scomp = sx - xcol;

    // DSMEM halo addresses (both parities)
    const uint32_t sa0 = cvta_smem(buf0);
    const uint32_t sa1 = cvta_smem(buf1);
    uint32_t nh0 = 0, nh1 = 0, sh0 = 0, sh1 = 0;
    if (rg == 0 && has_n) {
        const uint32_t off = (uint32_t)((ROWS - 1) * NXC + xcol) * 4u;
        nh0 = mapa_cluster(sa0 + off, rank - 1);
        nh1 = mapa_cluster(sa1 + off, rank - 1);
    }
    if (rg == RG - 1 && has_s) {
        const uint32_t off = (uint32_t)(xcol) * 4u;
        sh0 = mapa_cluster(sa0 + off, rank + 1);
        sh1 = mapa_cluster(sa1 + off, rank + 1);
    }

    // remote flag addresses (I am rank-1's south neighbor, rank+1's north one)
    uint32_t rf_n = 0, rf_s = 0;
    if (tid == 0) {
        if (has_n) rf_n = mapa_cluster(cvta_smem(&flag_s), rank - 1);
        if (has_s) rf_s = mapa_cluster(cvta_smem(&flag_n), rank + 1);
    }
    const uint32_t fa_n = cvta_smem(&flag_n);
    const uint32_t fa_s = cvta_smem(&flag_s);

    __syncthreads();
    const bool samp = (tid < rcnt);
    int roff = 0;
    float* outp = out;
    if (samp) {
        int2 e = rlist[tid];
        roff = e.x;
        outp = out + e.y;
    }

    cluster_sync_();  // zeroed buffers + flags visible cluster-wide

    // --- one FDTD step -------------------------------------------------------
    auto step = [&](const float* __restrict__ cur, float* __restrict__ nxt,
                    uint32_t nh, uint32_t sh, int t) {
        const int toff = (t + 2 < NT - 1) ? t + 2 : NT - 1;
        const float amp = xs[t] + xs[toff];

        // boundary row-groups wait until neighbor finished step t-1
        if (t > 0) {
            if (rg == 0 && has_n) {
                while (ld_flag_acq(fa_n) < (uint32_t)t) { }
            }
            if (rg == RG - 1 && has_s) {
                while (ld_flag_acq(fa_s) < (uint32_t)t) { }
            }
        }

        // row above the strip
        float4 vN;
        if (rg == 0) {
            vN = has_n ? ld_dsmem_v4(nh) : make_float4(0.f, 0.f, 0.f, 0.f);
        } else {
            vN = *(const float4*)(cur + (lr0 - 1) * NXC + xcol);
        }

#pragma unroll
        for (int j = 0; j < RPT; j++) {
            const int lr = lr0 + j;
            const float4 cc = cC[j];

            float4 vS;
            if (j < RPT - 1) {
                vS = cC[j + 1];
            } else if (rg == RG - 1) {
                vS = has_s ? ld_dsmem_v4(sh) : make_float4(0.f, 0.f, 0.f, 0.f);
            } else {
                vS = *(const float4*)(cur + (lr + 1) * NXC + xcol);
            }

            const float lft = (xcol > 0)       ? cur[lr * NXC + xcol - 1] : 0.f;
            const float rgt = (xcol + 4 < NXC) ? cur[lr * NXC + xcol + 4] : 0.f;

            float4 lap;
            lap.x = vN.x + vS.x + lft  + cc.y - 4.f * cc.x;
            lap.y = vN.y + vS.y + cc.x + cc.z - 4.f * cc.y;
            lap.z = vN.z + vS.z + cc.y + cc.w - 4.f * cc.z;
            lap.w = vN.w + vS.w + cc.z + rgt  - 4.f * cc.w;

            float4 nv;
            nv.x = 2.f * cc.x - pr[j].x + c2r[j].x * lap.x;
            nv.y = 2.f * cc.y - pr[j].y + c2r[j].y * lap.y;
            nv.z = 2.f * cc.z - pr[j].z + c2r[j].z * lap.z;
            nv.w = 2.f * cc.w - pr[j].w + c2r[j].w * lap.w;

            if (shere && j == sj) {
                if      (scomp == 0) nv.x += amp;
                else if (scomp == 1) nv.y += amp;
                else if (scomp == 2) nv.z += amp;
                else                 nv.w += amp;
            }

            *(float4*)(nxt + lr * NXC + xcol) = nv;
            pr[j] = cc;
            cC[j] = nv;
            vN = cc;
        }

        __syncthreads();   // all nxt stores visible CTA-wide

        // publish step t to neighbors
        if (tid == 0) {
            const uint32_t v = (uint32_t)(t + 1);
            if (has_n) st_flag_remote(rf_n, v);
            if (has_s) st_flag_remote(rf_s, v);
        }

        // owner-local receiver sampling from the freshly written buffer
        if (samp) {
            *outp = nxt[roff];
            outp += NS * NREC;
        }
    };

    // --- main time loop, unrolled x2 for compile-time buffer parity ----------
    for (int t2 = 0; t2 < NT; t2 += 2) {
        step(buf0, buf1, nh0, sh0, t2);
        step(buf1, buf0, nh1, sh1, t2 + 1);
    }

    cluster_sync_();  // keep cluster smem alive until all CTAs are done
}

// ---------------------------------------------------------------- launch
extern "C" void kernel_launch(void* const* d_in, const int* in_sizes, int n_in,
                              void* d_out, int out_size)
{
    const float* x   = (const float*)d_in[0];
    const float* vp  = (const float*)d_in[1];
    const int*   src = (const int*)d_in[2];
    const int*   rec = (const int*)d_in[3];
    float*       out = (float*)d_out;

    constexpr size_t SMEM16 = (size_t)(2 * (NZ / 16) * NXC + 512) * sizeof(float);
    constexpr size_t SMEM8  = (size_t)(2 * (NZ / 8)  * NXC + 512) * sizeof(float);

    cudaFuncSetAttribute((const void*)wave_kernel<16>,
                         cudaFuncAttributeMaxDynamicSharedMemorySize, (int)SMEM16);
    cudaFuncSetAttribute((const void*)wave_kernel<16>,
                         cudaFuncAttributeNonPortableClusterSizeAllowed, 1);
    cudaFuncSetAttribute((const void*)wave_kernel<8>,
                         cudaFuncAttributeMaxDynamicSharedMemorySize, (int)SMEM8);

    // deterministic capability probe for cluster size 16
    cudaLaunchConfig_t probe = {};
    probe.gridDim  = { NS * 16, 1, 1 };
    probe.blockDim = { NTHREADS, 1, 1 };
    probe.dynamicSmemBytes = SMEM16;
    int maxc = 0;
    cudaOccupancyMaxPotentialClusterSize(&maxc, wave_kernel<16>, &probe);

    cudaLaunchAttribute attr[1];
    attr[0].id = cudaLaunchAttributeClusterDimension;

    if (maxc >= 16) {
        cudaLaunchConfig_t cfg = {};
        cfg.gridDim  = { NS * 16, 1, 1 };
        cfg.blockDim = { NTHREADS, 1, 1 };
        cfg.dynamicSmemBytes = SMEM16;
        attr[0].val.clusterDim = { 16, 1, 1 };
        cfg.attrs = attr;
        cfg.numAttrs = 1;
        cudaLaunchKernelEx(&cfg, wave_kernel<16>, x, vp, src, rec, out);
    } else {
        cudaLaunchConfig_t cfg = {};
        cfg.gridDim  = { NS * 8, 1, 1 };
        cfg.blockDim = { NTHREADS, 1, 1 };
        cfg.dynamicSmemBytes = SMEM8;
        attr[0].val.clusterDim = { 8, 1, 1 };
        cfg.attrs = attr;
        cfg.numAttrs = 1;
        cudaLaunchKernelEx(&cfg, wave_kernel<8>, x, vp, src, rec, out);
    }
}

// round 8
// speedup vs baseline: 1.8236x; 1.8236x over previous
#include <cuda_runtime.h>
#include <cstdint>

// 2D acoustic FDTD, 500 steps, 8 shots, 256x256, 128 recs/shot.
// One persistent kernel; shot = 8-CTA cluster; field in SMEM + registers.
// One cluster.sync per step (proven fastest), owner-local receivers,
// packed f32x2 arithmetic (FFMA2) in the stencil.

#define DT 0.001f
#define DX 10.0f

constexpr int NT   = 500;
constexpr int NS   = 8;
constexpr int NZ   = 256;
constexpr int NXC  = 256;
constexpr int NREC = 128;

constexpr int CSZ  = 8;
constexpr int ROWS = NZ / CSZ;          // 32
constexpr int NTHREADS = 1024;
constexpr int COL4 = NXC / 4;           // 64
constexpr int RG   = NTHREADS / COL4;   // 16
constexpr int RPT  = ROWS / RG;         // 2

constexpr int BUF_ELEMS = ROWS * NXC;   // 8192
constexpr size_t SMEM_BYTES = (size_t)(2 * BUF_ELEMS + 512) * sizeof(float);

typedef unsigned long long u64;

// ---------------------------------------------------------------- PTX helpers
__device__ __forceinline__ uint32_t cvta_smem(const void* p) {
    return (uint32_t)__cvta_generic_to_shared(p);
}
__device__ __forceinline__ uint32_t mapa_cluster(uint32_t laddr, uint32_t rank) {
    uint32_t r;
    asm("mapa.shared::cluster.u32 %0, %1, %2;" : "=r"(r) : "r"(laddr), "r"(rank));
    return r;
}
__device__ __forceinline__ float4 ld_dsmem_v4(uint32_t addr) {
    float4 v;
    asm volatile("ld.shared::cluster.v4.f32 {%0,%1,%2,%3}, [%4];"
                 : "=f"(v.x), "=f"(v.y), "=f"(v.z), "=f"(v.w) : "r"(addr));
    return v;
}
__device__ __forceinline__ void cluster_sync_() {
    asm volatile("barrier.cluster.arrive.aligned;" ::: "memory");
    asm volatile("barrier.cluster.wait.aligned;" ::: "memory");
}
__device__ __forceinline__ uint32_t cluster_rank_() {
    uint32_t r;
    asm("mov.u32 %0, %%cluster_ctarank;" : "=r"(r));
    return r;
}

// ---- packed f32x2 ops -------------------------------------------------------
__device__ __forceinline__ u64 pk(float a, float b) {
    u64 r; asm("mov.b64 %0, {%1, %2};" : "=l"(r) : "f"(a), "f"(b)); return r;
}
__device__ __forceinline__ float2 upk(u64 v) {
    float2 f; asm("mov.b64 {%0, %1}, %2;" : "=f"(f.x), "=f"(f.y) : "l"(v)); return f;
}
__device__ __forceinline__ u64 addx2(u64 a, u64 b) {
    u64 r; asm("add.rn.f32x2 %0, %1, %2;" : "=l"(r) : "l"(a), "l"(b)); return r;
}
__device__ __forceinline__ u64 mulx2(u64 a, u64 b) {
    u64 r; asm("mul.rn.f32x2 %0, %1, %2;" : "=l"(r) : "l"(a), "l"(b)); return r;
}
__device__ __forceinline__ u64 fmax2(u64 a, u64 b, u64 c) {
    u64 r; asm("fma.rn.f32x2 %0, %1, %2, %3;" : "=l"(r) : "l"(a), "l"(b), "l"(c)); return r;
}

// ---------------------------------------------------------------- kernel
__global__ void __cluster_dims__(CSZ, 1, 1) __launch_bounds__(NTHREADS, 1)
wave_kernel(const float* __restrict__ x,     // (NT, NS)
            const float* __restrict__ vp,    // (NZ, NXC)
            const int*   __restrict__ src,   // (NS, 2)
            const int*   __restrict__ rec,   // (NS, NREC, 2)
            float*       __restrict__ out)   // (NT, NS, NREC)
{
    extern __shared__ float sm[];
    float* buf0 = sm;
    float* buf1 = sm + BUF_ELEMS;
    float* xs   = sm + 2 * BUF_ELEMS;

    __shared__ int rcnt;
    __shared__ int2 rlist[NREC];

    const int tid  = threadIdx.x;
    const uint32_t rank = cluster_rank_();
    const int shot = blockIdx.x / CSZ;

    const int col4 = tid & (COL4 - 1);
    const int rg   = tid >> 6;           // 0..15
    const int lr0  = rg * RPT;
    const int xcol = col4 * 4;
    const bool has_n = (rank > 0);
    const bool has_s = (rank < CSZ - 1);

    // --- init ----------------------------------------------------------------
    for (int i = tid; i < BUF_ELEMS; i += NTHREADS) { buf0[i] = 0.f; buf1[i] = 0.f; }
    for (int i = tid; i < NT; i += NTHREADS) xs[i] = x[i * NS + shot];
    if (tid == 0) rcnt = 0;
    __syncthreads();

    // claim receivers owned by this CTA
    if (tid < NREC) {
        const int gi = shot * NREC + tid;
        const int rz = rec[gi * 2 + 0];
        const int rx = rec[gi * 2 + 1];
        if ((uint32_t)(rz >> 5) == rank) {
            int s = atomicAdd(&rcnt, 1);
            rlist[s] = make_int2((rz & 31) * NXC + rx, shot * NREC + tid);
        }
    }

    // c2 in packed registers
    u64 k01[RPT], k23[RPT];
    const float sc = DT / DX;
#pragma unroll
    for (int j = 0; j < RPT; j++) {
        const int g = (int)rank * ROWS + lr0 + j;
        float4 v = *(const float4*)(vp + g * NXC + xcol);
        float a = v.x * sc, b = v.y * sc, c = v.z * sc, d = v.w * sc;
        k01[j] = pk(a * a, b * b);
        k23[j] = pk(c * c, d * d);
    }

    // packed constants
    const u64 TWO2  = pk(2.f, 2.f);
    const u64 NEG4  = pk(-4.f, -4.f);
    const u64 NEG1  = pk(-1.f, -1.f);

    // field registers: cur (float4) and negated prev (packed); zero at t=0
    float4 cC[RPT];
    u64 np01[RPT], np23[RPT];
#pragma unroll
    for (int j = 0; j < RPT; j++) {
        cC[j] = make_float4(0.f, 0.f, 0.f, 0.f);
        np01[j] = pk(0.f, 0.f);
        np23[j] = pk(0.f, 0.f);
    }

    // source ownership
    const int sz = src[shot * 2 + 0];
    const int sx = src[shot * 2 + 1];
    const int sj = sz - ((int)rank * ROWS + lr0);
    const bool shere = (sj >= 0 && sj < RPT && sx >= xcol && sx < xcol + 4);
    const int scomp = sx - xcol;

    // DSMEM halo addresses (both parities)
    const uint32_t sa0 = cvta_smem(buf0);
    const uint32_t sa1 = cvta_smem(buf1);
    uint32_t nh0 = 0, nh1 = 0, sh0 = 0, sh1 = 0;
    if (rg == 0 && has_n) {
        const uint32_t off = (uint32_t)((ROWS - 1) * NXC + xcol) * 4u;
        nh0 = mapa_cluster(sa0 + off, rank - 1);
        nh1 = mapa_cluster(sa1 + off, rank - 1);
    }
    if (rg == RG - 1 && has_s) {
        const uint32_t off = (uint32_t)(xcol) * 4u;
        sh0 = mapa_cluster(sa0 + off, rank + 1);
        sh1 = mapa_cluster(sa1 + off, rank + 1);
    }

    __syncthreads();
    const bool samp = (tid < rcnt);
    int roff = 0;
    float* outp = out;
    if (samp) {
        int2 e = rlist[tid];
        roff = e.x;
        outp = out + e.y;
    }

    cluster_sync_();  // zeroed buffers visible cluster-wide

    // --- one FDTD step (register field + packed f32x2 math) ------------------
    auto step = [&](const float* __restrict__ cur, float* __restrict__ nxt,
                    uint32_t nh, uint32_t sh, int t) {
        const int toff = (t + 2 < NT - 1) ? t + 2 : NT - 1;
        const float amp = xs[t] + xs[toff];

        // row above the strip (time-t values)
        float4 vN;
        if (rg == 0) {
            vN = has_n ? ld_dsmem_v4(nh) : make_float4(0.f, 0.f, 0.f, 0.f);
        } else {
            vN = *(const float4*)(cur + (lr0 - 1) * NXC + xcol);
        }
        u64 n01 = pk(vN.x, vN.y), n23 = pk(vN.z, vN.w);

#pragma unroll
        for (int j = 0; j < RPT; j++) {
            const int lr = lr0 + j;
            const float4 cc = cC[j];
            const u64 c01 = pk(cc.x, cc.y), c23 = pk(cc.z, cc.w);

            // south row (time-t)
            float4 vS;
            if (j < RPT - 1) {
                vS = cC[j + 1];
            } else if (rg == RG - 1) {
                vS = has_s ? ld_dsmem_v4(sh) : make_float4(0.f, 0.f, 0.f, 0.f);
            } else {
                vS = *(const float4*)(cur + (lr + 1) * NXC + xcol);
            }
            const u64 s01 = pk(vS.x, vS.y), s23 = pk(vS.z, vS.w);

            const float lft = (xcol > 0)       ? cur[lr * NXC + xcol - 1] : 0.f;
            const float rgt = (xcol + 4 < NXC) ? cur[lr * NXC + xcol + 4] : 0.f;

            // horizontal shift pairs
            const u64 L0 = pk(lft,  cc.x);   // (x-1, x)  for components x,y
            const u64 M  = pk(cc.y, cc.z);   // middle pair, shared
            const u64 R1 = pk(cc.w, rgt);    // (w, x+4)  for components z,w

            // lap = N + S + Lshift + Rshift - 4*C   (packed)
            u64 lap01 = addx2(addx2(n01, s01), addx2(L0, M));
            u64 lap23 = addx2(addx2(n23, s23), addx2(M, R1));
            lap01 = fmax2(c01, NEG4, lap01);
            lap23 = fmax2(c23, NEG4, lap23);

            // nv = 2*C - prev + c2*lap = fma(c2, lap, fma(2, C, -prev))
            const u64 nv01 = fmax2(k01[j], lap01, fmax2(c01, TWO2, np01[j]));
            const u64 nv23 = fmax2(k23[j], lap23, fmax2(c23, TWO2, np23[j]));

            // store negated prev for next step
            np01[j] = mulx2(c01, NEG1);
            np23[j] = mulx2(c23, NEG1);

            const float2 a = upk(nv01), b = upk(nv23);
            float4 nv = make_float4(a.x, a.y, b.x, b.y);

            if (shere && j == sj) {
                if      (scomp == 0) nv.x += amp;
                else if (scomp == 1) nv.y += amp;
                else if (scomp == 2) nv.z += amp;
                else                 nv.w += amp;
            }

            *(float4*)(nxt + lr * NXC + xcol) = nv;
            cC[j] = nv;
            n01 = c01; n23 = c23;
        }

        cluster_sync_();  // release my nxt stores, acquire everyone's

        if (samp) {
            *outp = nxt[roff];
            outp += NS * NREC;
        }
    };

    // --- main time loop, unrolled x2 for compile-time buffer parity ----------
    for (int t2 = 0; t2 < NT; t2 += 2) {
        step(buf0, buf1, nh0, sh0, t2);
        step(buf1, buf0, nh1, sh1, t2 + 1);
    }
}

// ---------------------------------------------------------------- launch
extern "C" void kernel_launch(void* const* d_in, const int* in_sizes, int n_in,
                              void* d_out, int out_size)
{
    const float* x   = (const float*)d_in[0];
    const float* vp  = (const float*)d_in[1];
    const int*   src = (const int*)d_in[2];
    const int*   rec = (const int*)d_in[3];
    float*       out = (float*)d_out;

    cudaFuncSetAttribute((const void*)wave_kernel,
                         cudaFuncAttributeMaxDynamicSharedMemorySize,
                         (int)SMEM_BYTES);

    wave_kernel<<<NS * CSZ, NTHREADS, SMEM_BYTES>>>(x, vp, src, rec, out);
}